// round 5
// baseline (speedup 1.0000x reference)
#include <cuda_runtime.h>
#include <cuda_bf16.h>
#include <cstdint>

// MultiScaleDeformableAttention, fully-static shapes.
// value:               (B=2, Len=21760, nH=8, D=32)   f32   d_in[0]
// sampling_locations:  (B, Q=21760, nH, L=4, P=4, 2)  f32   d_in[3]
// attention_weights:   (B, Q, nH, L, P)               f32   d_in[4]
// out: (B, Q, nH*D=256) f32
//
// R4: 1 warp = 8 queries (same b,h). lane = g*4 + lr; group g (0..7) owns
// query q0+g, lane lr (0..3) owns 8 channels d=[8*lr, 8*lr+8) loaded with
// one 256-bit LDG (sm_100a ld.global.nc.v8.b32). Per-sample scalar math is
// now shared across 8 queries (was 4) -> issue/ALU per gathered byte ~halved.
// Each corner-load instruction covers 8 full 128B lines (4 lanes x 32B each)
// so L1 wavefront efficiency is unchanged. Dual accumulators halve the FFMA
// dependency chain.

#define BB   2
#define NH   8
#define QQ   21760
#define LEN  21760

__device__ __forceinline__ void ldg256(const float* p, float v[8]) {
    unsigned r0, r1, r2, r3, r4, r5, r6, r7;
    asm("ld.global.nc.v8.b32 {%0,%1,%2,%3,%4,%5,%6,%7}, [%8];"
        : "=r"(r0), "=r"(r1), "=r"(r2), "=r"(r3),
          "=r"(r4), "=r"(r5), "=r"(r6), "=r"(r7)
        : "l"(p));
    v[0] = __uint_as_float(r0); v[1] = __uint_as_float(r1);
    v[2] = __uint_as_float(r2); v[3] = __uint_as_float(r3);
    v[4] = __uint_as_float(r4); v[5] = __uint_as_float(r5);
    v[6] = __uint_as_float(r6); v[7] = __uint_as_float(r7);
}

__device__ __forceinline__ void stg256(float* p, const float v[8]) {
    asm volatile("st.global.v8.b32 [%0], {%1,%2,%3,%4,%5,%6,%7,%8};"
        :: "l"(p),
           "r"(__float_as_uint(v[0])), "r"(__float_as_uint(v[1])),
           "r"(__float_as_uint(v[2])), "r"(__float_as_uint(v[3])),
           "r"(__float_as_uint(v[4])), "r"(__float_as_uint(v[5])),
           "r"(__float_as_uint(v[6])), "r"(__float_as_uint(v[7]))
        : "memory");
}

__global__ void __launch_bounds__(256) msda_kernel(
    const float* __restrict__ value,
    const float* __restrict__ loc,
    const float* __restrict__ attw,
    float* __restrict__ out)
{
    constexpr int LH[4] = {128, 64, 32, 16};
    constexpr int LW[4] = {128, 64, 32, 16};
    constexpr int LS[4] = {0, 16384, 20480, 21504};

    const int tid  = blockIdx.x * blockDim.x + threadIdx.x;
    const int w    = tid >> 5;          // global warp id
    const int lane = tid & 31;
    const int g    = lane >> 2;         // query group 0..7
    const int lr   = lane & 3;          // 8-channel slice 0..3

    const int q8 = w % (QQ / 8);
    const int bh = w / (QQ / 8);
    const int b  = bh >> 3;
    const int h  = bh & 7;
    const int q  = q8 * 8 + g;

    // per-query parameter vectors, distributed across the 4 lanes of the group
    const size_t qbase = ((size_t)(b * QQ + q) * NH + h);
    float lv[8];                                   // 8 of the 32 loc floats
    ldg256(loc + qbase * 32 + lr * 8, lv);
    const float4 av = __ldg((const float4*)(attw + qbase * 16) + lr);
    float avf[4] = {av.x, av.y, av.z, av.w};

    // value base for (b,h) with this lane's channel slice folded in (f32 units)
    const float* vb  = value + (size_t)b * (LEN * 256) + h * 32 + lr * 8;
    const float* vl0 = vb + (size_t)LS[0] * 256;
    const float* vl1 = vb + (size_t)LS[1] * 256;
    const float* vl2 = vb + (size_t)LS[2] * 256;
    const float* vl3 = vb + (size_t)LS[3] * 256;

    float accA[8] = {0.f, 0.f, 0.f, 0.f, 0.f, 0.f, 0.f, 0.f};
    float accB[8] = {0.f, 0.f, 0.f, 0.f, 0.f, 0.f, 0.f, 0.f};

#pragma unroll
    for (int s = 0; s < 16; ++s) {
        const int l  = s >> 2;
        const int Wl = LW[l], Hl = LH[l];
        const float* vl = (l == 0) ? vl0 : (l == 1) ? vl1 : (l == 2) ? vl2 : vl3;

        // distribute (x, y, aw): sample s of group's query lives in lane
        // owner = g*4 + (s>>2); component indices are compile-time constants.
        const int owner = (g << 2) + (s >> 2);
        const int cx = (2 * s) & 7;                // x component in lv
        const float xr = __shfl_sync(0xffffffffu, lv[cx],     owner);
        const float yr = __shfl_sync(0xffffffffu, lv[cx + 1], owner);
        const float aw = __shfl_sync(0xffffffffu, avf[s & 3], owner);

        // pixel-space coords: x = loc*W - 0.5 ; x in [-0.5, W-0.5)
        const float x  = fmaf(xr, (float)Wl, -0.5f);
        const float y  = fmaf(yr, (float)Hl, -0.5f);
        const int   x0 = __float2int_rd(x);
        const int   y0 = __float2int_rd(y);
        const float wx1 = x - __int2float_rn(x0);
        const float wy1 = y - __int2float_rn(y0);

        // only left/top (x0=-1) and right/bottom (x1=W) can be OOB
        const float wx0  = (x >= 0.f)            ? (1.f - wx1) : 0.f;
        const float wx1s = (x < (float)(Wl - 1)) ? wx1         : 0.f;
        const float wy0  = (y >= 0.f)            ? (1.f - wy1) : 0.f;
        const float wy1s = (y < (float)(Hl - 1)) ? wy1         : 0.f;

        const int xc0 = max(x0, 0);
        const int xc1 = min(x0 + 1, Wl - 1);
        const int yc0 = max(y0, 0);
        const int yc1 = min(y0 + 1, Hl - 1);

        const float a0 = aw * wy0;
        const float a1 = aw * wy1s;
        const float w00 = wx0  * a0;
        const float w10 = wx1s * a0;
        const float w01 = wx0  * a1;
        const float w11 = wx1s * a1;

        const int r0 = yc0 * Wl;
        const int r1 = yc1 * Wl;

        float v00[8], v10[8], v01[8], v11[8];
        ldg256(vl + (size_t)(r0 + xc0) * 256, v00);
        ldg256(vl + (size_t)(r0 + xc1) * 256, v10);
        ldg256(vl + (size_t)(r1 + xc0) * 256, v01);
        ldg256(vl + (size_t)(r1 + xc1) * 256, v11);

#pragma unroll
        for (int k = 0; k < 8; ++k) {
            accA[k] = fmaf(w00, v00[k], fmaf(w10, v10[k], accA[k]));
            accB[k] = fmaf(w01, v01[k], fmaf(w11, v11[k], accB[k]));
        }
    }

    float o[8];
#pragma unroll
    for (int k = 0; k < 8; ++k) o[k] = accA[k] + accB[k];

    // out[b][q][h*32 + lr*8 .. +7]
    stg256(out + (size_t)(b * QQ + q) * 256 + h * 32 + lr * 8, o);
}

extern "C" void kernel_launch(void* const* d_in, const int* in_sizes, int n_in,
                              void* d_out, int out_size)
{
    const float* value = (const float*)d_in[0];
    const float* loc   = (const float*)d_in[3];
    const float* attw  = (const float*)d_in[4];
    float* out = (float*)d_out;

    // total warps = B*NH*(Q/8) = 43520 ; 8 warps/block -> 5440 blocks
    const int total_threads = BB * NH * (QQ / 8) * 32;
    const int block = 256;
    const int grid  = total_threads / block;
    msda_kernel<<<grid, block>>>(value, loc, attw, out);
}